// round 3
// baseline (speedup 1.0000x reference)
#include <cuda_runtime.h>

#define SEQLEN 512
#define BATCH  64
#define INP    1024
#define HID    1024
#define G4     4096

// ---- device scratch (static; no runtime allocation allowed) ----
__device__ float g_G[(size_t)SEQLEN * BATCH * G4];   // x@W_ih^T + b_ih + b_hh
__device__ float g_h0[BATCH * HID];
__device__ float g_h1[BATCH * HID];
__device__ float g_c [BATCH * HID];

// ---- zero h0 and c every call (deterministic) ----
__global__ void zero_state_kernel() {
    int i = blockIdx.x * blockDim.x + threadIdx.x;
    if (i < BATCH * HID) { g_h0[i] = 0.0f; g_c[i] = 0.0f; }
}

// ---- big input GEMM: G = X @ W_ih^T + (b_ih + b_hh) ----
// M=32768, N=4096, K=1024. 128x128 tile, BK=8, 256 threads, 8x8 per thread.
__global__ __launch_bounds__(256) void gemm_gates(
    const float* __restrict__ X,     // [SEQLEN*BATCH][INP]
    const float* __restrict__ Wih,   // [G4][INP]
    const float* __restrict__ bih,
    const float* __restrict__ bhh)
{
    __shared__ __align__(16) float As[8][132];
    __shared__ __align__(16) float Bs[8][132];

    const int tid = threadIdx.x;
    const int bn = blockIdx.x;   // 0..31
    const int bm = blockIdx.y;   // 0..255

    const int lr = tid >> 1;           // 0..127
    const int lk = (tid & 1) << 2;     // 0 or 4
    const float* Ag = X   + (size_t)(bm * 128 + lr) * INP + lk;
    const float* Bg = Wih + (size_t)(bn * 128 + lr) * INP + lk;

    const int tx = tid & 15;
    const int ty = tid >> 4;

    float acc[8][8];
    #pragma unroll
    for (int i = 0; i < 8; i++)
        #pragma unroll
        for (int j = 0; j < 8; j++) acc[i][j] = 0.0f;

    for (int k0 = 0; k0 < INP; k0 += 8) {
        float4 av = *(const float4*)(Ag + k0);
        float4 bv = *(const float4*)(Bg + k0);
        __syncthreads();
        As[lk+0][lr] = av.x; As[lk+1][lr] = av.y; As[lk+2][lr] = av.z; As[lk+3][lr] = av.w;
        Bs[lk+0][lr] = bv.x; Bs[lk+1][lr] = bv.y; Bs[lk+2][lr] = bv.z; Bs[lk+3][lr] = bv.w;
        __syncthreads();

        #pragma unroll
        for (int kk = 0; kk < 8; kk++) {
            float4 a0 = *(const float4*)&As[kk][ty * 8];
            float4 a1 = *(const float4*)&As[kk][ty * 8 + 4];
            float4 b0 = *(const float4*)&Bs[kk][tx * 8];
            float4 b1 = *(const float4*)&Bs[kk][tx * 8 + 4];
            float a[8] = {a0.x,a0.y,a0.z,a0.w,a1.x,a1.y,a1.z,a1.w};
            float b[8] = {b0.x,b0.y,b0.z,b0.w,b1.x,b1.y,b1.z,b1.w};
            #pragma unroll
            for (int i = 0; i < 8; i++)
                #pragma unroll
                for (int j = 0; j < 8; j++)
                    acc[i][j] += a[i] * b[j];
        }
    }

    const int col0 = bn * 128 + tx * 8;
    float bias[8];
    #pragma unroll
    for (int j = 0; j < 8; j++) bias[j] = bih[col0 + j] + bhh[col0 + j];

    #pragma unroll
    for (int i = 0; i < 8; i++) {
        int row = bm * 128 + ty * 8 + i;
        float4 o0 = make_float4(acc[i][0]+bias[0], acc[i][1]+bias[1],
                                acc[i][2]+bias[2], acc[i][3]+bias[3]);
        float4 o1 = make_float4(acc[i][4]+bias[4], acc[i][5]+bias[5],
                                acc[i][6]+bias[6], acc[i][7]+bias[7]);
        *(float4*)&g_G[(size_t)row * G4 + col0    ] = o0;
        *(float4*)&g_G[(size_t)row * G4 + col0 + 4] = o1;
    }
}

// ---- one recurrent step ----
// 128 CTAs; CTA owns 8 hidden units -> 32 W_hh rows (4 gates x 8 units).
// 256 threads = 8 warps; warp w handles batches [8w,8w+8); lane = gate*8+unit.
__global__ __launch_bounds__(256) void lstm_step(
    const float* __restrict__ Whh,       // [G4][HID]
    const float* __restrict__ keep,      // [SEQLEN][BATCH][HID]
    const int*   __restrict__ training,
    float*       __restrict__ final_out,
    int t)
{
    __shared__ __align__(16) float hs[64][68];   // h chunk [batch][k]
    __shared__ float Ws[32][65];                 // W chunk [gate*8+unit][k]

    const int tid  = threadIdx.x;
    const int j0   = blockIdx.x * 8;
    const int w    = tid >> 5;
    const int lane = tid & 31;
    const int gsel = lane >> 3;
    const int u    = lane & 7;

    const float* hin  = (t & 1) ? g_h1 : g_h0;
    float*       hout = (t == SEQLEN - 1) ? final_out : ((t & 1) ? g_h0 : g_h1);

    // loader coords
    const int hb = tid >> 2;            // 0..63
    const int hk = (tid & 3) << 4;      // 0,16,32,48
    const int wr = tid >> 3;            // 0..31
    const int wk = (tid & 7) << 3;      // 0..56
    const int grow = (wr >> 3) * HID + j0 + (wr & 7);

    float acc[8];
    #pragma unroll
    for (int i = 0; i < 8; i++) acc[i] = 0.0f;

    for (int k0 = 0; k0 < HID; k0 += 64) {
        __syncthreads();
        // load h chunk: 64x64 floats
        #pragma unroll
        for (int q = 0; q < 4; q++) {
            float4 v = *(const float4*)(hin + hb * HID + k0 + hk + 4 * q);
            *(float4*)&hs[hb][hk + 4 * q] = v;
        }
        // load W chunk: 32x64 floats (scalar stores, pad 65)
        #pragma unroll
        for (int q = 0; q < 2; q++) {
            float4 v = *(const float4*)(Whh + (size_t)grow * HID + k0 + wk + 4 * q);
            Ws[wr][wk + 4*q + 0] = v.x; Ws[wr][wk + 4*q + 1] = v.y;
            Ws[wr][wk + 4*q + 2] = v.z; Ws[wr][wk + 4*q + 3] = v.w;
        }
        __syncthreads();

        #pragma unroll
        for (int k = 0; k < 64; k += 4) {
            float w0 = Ws[lane][k+0], w1 = Ws[lane][k+1];
            float w2 = Ws[lane][k+2], w3 = Ws[lane][k+3];
            #pragma unroll
            for (int i = 0; i < 8; i++) {
                float4 hv = *(const float4*)&hs[w * 8 + i][k];
                acc[i] += w0*hv.x + w1*hv.y + w2*hv.z + w3*hv.w;
            }
        }
    }

    const int   trn   = *training;
    const float scale = trn ? (1.0f / 0.9f) : 1.0f;
    const float* Gt   = g_G + (size_t)t * BATCH * G4;

    #pragma unroll
    for (int i = 0; i < 8; i++) {
        const int b = w * 8 + i;
        float v = acc[i] + Gt[(size_t)b * G4 + gsel * HID + j0 + u];
        // lanes 0..7 (gate i) gather f,g,o from lanes +8,+16,+24
        float fv = __shfl_sync(0xffffffffu, v, lane + 8);
        float gv = __shfl_sync(0xffffffffu, v, lane + 16);
        float ov = __shfl_sync(0xffffffffu, v, lane + 24);
        if (lane < 8) {
            const int j = j0 + u;
            float ig = 1.0f / (1.0f + __expf(-v));
            float fg = 1.0f / (1.0f + __expf(-fv));
            float gg = tanhf(gv);
            float og = 1.0f / (1.0f + __expf(-ov));
            float c  = fg * g_c[b * HID + j] + ig * gg;
            g_c[b * HID + j] = c;
            float h = og * tanhf(c);
            if (trn) h *= keep[(size_t)t * BATCH * HID + b * HID + j] * scale;
            hout[b * HID + j] = h;
        }
    }
}

extern "C" void kernel_launch(void* const* d_in, const int* in_sizes, int n_in,
                              void* d_out, int out_size) {
    const float* x    = (const float*)d_in[0];
    const float* keep = (const float*)d_in[1];
    const float* Wih  = (const float*)d_in[2];
    const float* Whh  = (const float*)d_in[3];
    const float* bih  = (const float*)d_in[4];
    const float* bhh  = (const float*)d_in[5];
    const int*   trn  = (const int*)d_in[6];
    float* out = (float*)d_out;

    zero_state_kernel<<<256, 256>>>();
    dim3 g1(32, 256);
    gemm_gates<<<g1, 256>>>(x, Wih, bih, bhh);
    for (int t = 0; t < SEQLEN; t++)
        lstm_step<<<128, 256>>>(Whh, keep, trn, out, t);
}

// round 4
// speedup vs baseline: 1.0497x; 1.0497x over previous
#include <cuda_runtime.h>

#define SEQLEN 512
#define BATCH  64
#define INP    1024
#define HID    1024
#define G4     4096

// ---- device scratch (static; no runtime allocation allowed) ----
__device__ float g_G[(size_t)SEQLEN * BATCH * G4];   // x@W_ih^T + b_ih + b_hh
__device__ float g_h0[BATCH * HID];
__device__ float g_h1[BATCH * HID];
__device__ float g_c [BATCH * HID];

// ---- packed f32x2 FFMA (Blackwell-only, PTX path) ----
static __device__ __forceinline__ void ffma2(unsigned long long& a,
                                             unsigned long long x,
                                             unsigned long long y) {
    asm("fma.rn.f32x2 %0, %1, %2, %0;" : "+l"(a) : "l"(x), "l"(y));
}
static __device__ __forceinline__ unsigned long long pack2(float x, float y) {
    unsigned long long r;
    asm("mov.b64 %0, {%1, %2};" : "=l"(r) : "f"(x), "f"(y));
    return r;
}
static __device__ __forceinline__ float2 unpack2(unsigned long long v) {
    float lo, hi;
    asm("mov.b64 {%0, %1}, %2;" : "=f"(lo), "=f"(hi) : "l"(v));
    return make_float2(lo, hi);
}

__global__ void zero_state_kernel() {
    int i = blockIdx.x * blockDim.x + threadIdx.x;
    if (i < BATCH * HID) { g_h0[i] = 0.0f; g_c[i] = 0.0f; }
}

// ---- big input GEMM: G = X @ W_ih^T + (b_ih + b_hh) ----
// M=32768, N=4096, K=1024. 128x128 tile, BK=8, 256 threads, 8x8/thread, f32x2 over j.
__global__ __launch_bounds__(256) void gemm_gates(
    const float* __restrict__ X,
    const float* __restrict__ Wih,
    const float* __restrict__ bih,
    const float* __restrict__ bhh)
{
    __shared__ __align__(16) float As[8][132];
    __shared__ __align__(16) float Bs[8][132];

    const int tid = threadIdx.x;
    const int bn = blockIdx.x;
    const int bm = blockIdx.y;

    const int lr = tid >> 1;
    const int lk = (tid & 1) << 2;
    const float* Ag = X   + (size_t)(bm * 128 + lr) * INP + lk;
    const float* Bg = Wih + (size_t)(bn * 128 + lr) * INP + lk;

    const int tx = tid & 15;
    const int ty = tid >> 4;

    unsigned long long acc[8][4];
    #pragma unroll
    for (int i = 0; i < 8; i++)
        #pragma unroll
        for (int j = 0; j < 4; j++) acc[i][j] = 0ull;

    for (int k0 = 0; k0 < INP; k0 += 8) {
        float4 av = *(const float4*)(Ag + k0);
        float4 bv = *(const float4*)(Bg + k0);
        __syncthreads();
        As[lk+0][lr] = av.x; As[lk+1][lr] = av.y; As[lk+2][lr] = av.z; As[lk+3][lr] = av.w;
        Bs[lk+0][lr] = bv.x; Bs[lk+1][lr] = bv.y; Bs[lk+2][lr] = bv.z; Bs[lk+3][lr] = bv.w;
        __syncthreads();

        #pragma unroll
        for (int kk = 0; kk < 8; kk++) {
            float4 a0 = *(const float4*)&As[kk][ty * 8];
            float4 a1 = *(const float4*)&As[kk][ty * 8 + 4];
            ulonglong2 b0 = *(const ulonglong2*)&Bs[kk][tx * 8];
            ulonglong2 b1 = *(const ulonglong2*)&Bs[kk][tx * 8 + 4];
            float a[8] = {a0.x,a0.y,a0.z,a0.w,a1.x,a1.y,a1.z,a1.w};
            #pragma unroll
            for (int i = 0; i < 8; i++) {
                unsigned long long aa = pack2(a[i], a[i]);
                ffma2(acc[i][0], aa, b0.x);
                ffma2(acc[i][1], aa, b0.y);
                ffma2(acc[i][2], aa, b1.x);
                ffma2(acc[i][3], aa, b1.y);
            }
        }
    }

    const int col0 = bn * 128 + tx * 8;
    float bias[8];
    #pragma unroll
    for (int j = 0; j < 8; j++) bias[j] = bih[col0 + j] + bhh[col0 + j];

    #pragma unroll
    for (int i = 0; i < 8; i++) {
        int row = bm * 128 + ty * 8 + i;
        float2 p0 = unpack2(acc[i][0]);
        float2 p1 = unpack2(acc[i][1]);
        float2 p2 = unpack2(acc[i][2]);
        float2 p3 = unpack2(acc[i][3]);
        float4 o0 = make_float4(p0.x+bias[0], p0.y+bias[1], p1.x+bias[2], p1.y+bias[3]);
        float4 o1 = make_float4(p2.x+bias[4], p2.y+bias[5], p3.x+bias[6], p3.y+bias[7]);
        *(float4*)&g_G[(size_t)row * G4 + col0    ] = o0;
        *(float4*)&g_G[(size_t)row * G4 + col0 + 4] = o1;
    }
}

// ---- one recurrent step: double-buffered, f32x2 k-paired ----
// 128 CTAs; CTA owns 8 hidden units -> 32 W_hh rows. 256 thr = 8 warps;
// warp w handles batches [8w,8w+8); lane = gate*8+unit.
__global__ __launch_bounds__(256) void lstm_step(
    const float* __restrict__ Whh,
    const float* __restrict__ keep,
    const int*   __restrict__ training,
    float*       __restrict__ final_out,
    int t)
{
    __shared__ __align__(16) float hs[2][64][68];               // h chunk [batch][k]
    __shared__ __align__(16) unsigned long long Wp[2][32][34];  // W chunk, k-paired

    const int tid  = threadIdx.x;
    const int j0   = blockIdx.x * 8;
    const int w    = tid >> 5;
    const int lane = tid & 31;
    const int gsel = lane >> 3;
    const int u    = lane & 7;

    const float* hin  = (t & 1) ? g_h1 : g_h0;
    float*       hout = (t == SEQLEN - 1) ? final_out : ((t & 1) ? g_h0 : g_h1);

    // loader coords
    const int hb = tid >> 2;            // 0..63 (batch row)
    const int hk = (tid & 3) << 4;      // 0,16,32,48
    const int wr = tid >> 3;            // 0..31 (W row within CTA)
    const int wk = (tid & 7) << 3;      // 0..56
    const int grow = (wr >> 3) * HID + j0 + (wr & 7);
    const float* hptr = hin + hb * HID + hk;
    const float* wptr = Whh + (size_t)grow * HID + wk;

    unsigned long long acc[8];
    #pragma unroll
    for (int i = 0; i < 8; i++) acc[i] = 0ull;

    // prologue: load chunk 0
    float4 hreg[4], wreg[2];
    #pragma unroll
    for (int q = 0; q < 4; q++) hreg[q] = *(const float4*)(hptr + 4 * q);
    #pragma unroll
    for (int q = 0; q < 2; q++) wreg[q] = *(const float4*)(wptr + 4 * q);
    #pragma unroll
    for (int q = 0; q < 4; q++) *(float4*)&hs[0][hb][hk + 4 * q] = hreg[q];
    #pragma unroll
    for (int q = 0; q < 2; q++) *(float4*)&Wp[0][wr][(wk >> 1) + 2 * q] = wreg[q];

    int buf = 0;
    for (int c = 0; c < 16; c++) {
        __syncthreads();
        // issue gmem loads for next chunk before compute (latency hiding)
        if (c < 15) {
            const int k1 = (c + 1) * 64;
            #pragma unroll
            for (int q = 0; q < 4; q++) hreg[q] = *(const float4*)(hptr + k1 + 4 * q);
            #pragma unroll
            for (int q = 0; q < 2; q++) wreg[q] = *(const float4*)(wptr + k1 + 4 * q);
        }
        // compute current chunk
        #pragma unroll
        for (int kk = 0; kk < 64; kk += 4) {
            ulonglong2 wv = *(const ulonglong2*)&Wp[buf][lane][kk >> 1];
            #pragma unroll
            for (int i = 0; i < 8; i++) {
                ulonglong2 hv = *(const ulonglong2*)&hs[buf][w * 8 + i][kk];
                ffma2(acc[i], wv.x, hv.x);
                ffma2(acc[i], wv.y, hv.y);
            }
        }
        // stage next chunk into other buffer
        if (c < 15) {
            const int nb = buf ^ 1;
            #pragma unroll
            for (int q = 0; q < 4; q++) *(float4*)&hs[nb][hb][hk + 4 * q] = hreg[q];
            #pragma unroll
            for (int q = 0; q < 2; q++) *(float4*)&Wp[nb][wr][(wk >> 1) + 2 * q] = wreg[q];
        }
        buf ^= 1;
    }

    const int   trn   = *training;
    const float scale = trn ? (1.0f / 0.9f) : 1.0f;
    const float* Gt   = g_G + (size_t)t * BATCH * G4;

    #pragma unroll
    for (int i = 0; i < 8; i++) {
        const int b = w * 8 + i;
        float2 p = unpack2(acc[i]);
        float v = p.x + p.y + Gt[(size_t)b * G4 + gsel * HID + j0 + u];
        float fv = __shfl_sync(0xffffffffu, v, lane + 8);
        float gv = __shfl_sync(0xffffffffu, v, lane + 16);
        float ov = __shfl_sync(0xffffffffu, v, lane + 24);
        if (lane < 8) {
            const int j = j0 + u;
            float ig = 1.0f / (1.0f + __expf(-v));
            float fg = 1.0f / (1.0f + __expf(-fv));
            float gg = tanhf(gv);
            float og = 1.0f / (1.0f + __expf(-ov));
            float cc = fg * g_c[b * HID + j] + ig * gg;
            g_c[b * HID + j] = cc;
            float h = og * tanhf(cc);
            if (trn) h *= keep[(size_t)t * BATCH * HID + b * HID + j] * scale;
            hout[b * HID + j] = h;
        }
    }
}

extern "C" void kernel_launch(void* const* d_in, const int* in_sizes, int n_in,
                              void* d_out, int out_size) {
    const float* x    = (const float*)d_in[0];
    const float* keep = (const float*)d_in[1];
    const float* Wih  = (const float*)d_in[2];
    const float* Whh  = (const float*)d_in[3];
    const float* bih  = (const float*)d_in[4];
    const float* bhh  = (const float*)d_in[5];
    const int*   trn  = (const int*)d_in[6];
    float* out = (float*)d_out;

    zero_state_kernel<<<256, 256>>>();
    dim3 g1(32, 256);
    gemm_gates<<<g1, 256>>>(x, Wih, bih, bhh);
    for (int t = 0; t < SEQLEN; t++)
        lstm_step<<<128, 256>>>(Whh, keep, trn, out, t);
}

// round 5
// speedup vs baseline: 1.3087x; 1.2467x over previous
#include <cuda_runtime.h>

#define SEQLEN 512
#define BATCH  64
#define INP    1024
#define HID    1024
#define G4     4096
#define NCTA   128

typedef unsigned long long ull;

// ---- device scratch (static; no runtime allocation allowed) ----
__device__ float g_G[(size_t)SEQLEN * BATCH * G4];   // x@W_ih^T + b_ih + b_hh
__device__ float g_h0[BATCH * HID];
__device__ float g_h1[BATCH * HID];
__device__ unsigned int g_bar;

// ---- packed f32x2 FFMA (Blackwell PTX path) ----
static __device__ __forceinline__ void ffma2(ull& a, ull x, ull y) {
    asm("fma.rn.f32x2 %0, %1, %2, %0;" : "+l"(a) : "l"(x), "l"(y));
}
static __device__ __forceinline__ ull pack2(float x, float y) {
    ull r; asm("mov.b64 %0, {%1, %2};" : "=l"(r) : "f"(x), "f"(y)); return r;
}
static __device__ __forceinline__ float2 unpack2(ull v) {
    float lo, hi; asm("mov.b64 {%0, %1}, %2;" : "=f"(lo), "=f"(hi) : "l"(v));
    return make_float2(lo, hi);
}

__global__ void zero_state_kernel() {
    int i = blockIdx.x * blockDim.x + threadIdx.x;
    if (i < BATCH * HID) { g_h0[i] = 0.0f; }
    if (i == 0) g_bar = 0u;
}

// ---- big input GEMM: G = X @ W_ih^T + (b_ih + b_hh)  (proven in R3/R4) ----
__global__ __launch_bounds__(256) void gemm_gates(
    const float* __restrict__ X,
    const float* __restrict__ Wih,
    const float* __restrict__ bih,
    const float* __restrict__ bhh)
{
    __shared__ __align__(16) float As[8][132];
    __shared__ __align__(16) float Bs[8][132];

    const int tid = threadIdx.x;
    const int bn = blockIdx.x;
    const int bm = blockIdx.y;

    const int lr = tid >> 1;
    const int lk = (tid & 1) << 2;
    const float* Ag = X   + (size_t)(bm * 128 + lr) * INP + lk;
    const float* Bg = Wih + (size_t)(bn * 128 + lr) * INP + lk;

    const int tx = tid & 15;
    const int ty = tid >> 4;

    ull acc[8][4];
    #pragma unroll
    for (int i = 0; i < 8; i++)
        #pragma unroll
        for (int j = 0; j < 4; j++) acc[i][j] = 0ull;

    for (int k0 = 0; k0 < INP; k0 += 8) {
        float4 av = *(const float4*)(Ag + k0);
        float4 bv = *(const float4*)(Bg + k0);
        __syncthreads();
        As[lk+0][lr] = av.x; As[lk+1][lr] = av.y; As[lk+2][lr] = av.z; As[lk+3][lr] = av.w;
        Bs[lk+0][lr] = bv.x; Bs[lk+1][lr] = bv.y; Bs[lk+2][lr] = bv.z; Bs[lk+3][lr] = bv.w;
        __syncthreads();

        #pragma unroll
        for (int kk = 0; kk < 8; kk++) {
            float4 a0 = *(const float4*)&As[kk][ty * 8];
            float4 a1 = *(const float4*)&As[kk][ty * 8 + 4];
            ulonglong2 b0 = *(const ulonglong2*)&Bs[kk][tx * 8];
            ulonglong2 b1 = *(const ulonglong2*)&Bs[kk][tx * 8 + 4];
            float a[8] = {a0.x,a0.y,a0.z,a0.w,a1.x,a1.y,a1.z,a1.w};
            #pragma unroll
            for (int i = 0; i < 8; i++) {
                ull aa = pack2(a[i], a[i]);
                ffma2(acc[i][0], aa, b0.x);
                ffma2(acc[i][1], aa, b0.y);
                ffma2(acc[i][2], aa, b1.x);
                ffma2(acc[i][3], aa, b1.y);
            }
        }
    }

    const int col0 = bn * 128 + tx * 8;
    float bias[8];
    #pragma unroll
    for (int j = 0; j < 8; j++) bias[j] = bih[col0 + j] + bhh[col0 + j];

    #pragma unroll
    for (int i = 0; i < 8; i++) {
        int row = bm * 128 + ty * 8 + i;
        float2 p0 = unpack2(acc[i][0]);
        float2 p1 = unpack2(acc[i][1]);
        float2 p2 = unpack2(acc[i][2]);
        float2 p3 = unpack2(acc[i][3]);
        float4 o0 = make_float4(p0.x+bias[0], p0.y+bias[1], p1.x+bias[2], p1.y+bias[3]);
        float4 o1 = make_float4(p2.x+bias[4], p2.y+bias[5], p3.x+bias[6], p3.y+bias[7]);
        *(float4*)&g_G[(size_t)row * G4 + col0    ] = o0;
        *(float4*)&g_G[(size_t)row * G4 + col0 + 4] = o1;
    }
}

// ---- persistent recurrence: all 512 steps in ONE kernel ----
// 128 CTAs x 256 thr, 1 CTA/SM (smem-limited) -> all co-resident, grid barrier safe.
// CTA owns 8 hidden units (32 W_hh rows) cached in smem for the whole kernel.
#define WPAD 514   // u64 row stride: 514*8B = 257*16B, 257 % 8 == 1 -> conflict-free
__global__ __launch_bounds__(256) void lstm_persist(
    const float* __restrict__ Whh,
    const float* __restrict__ keep,
    const int*   __restrict__ training,
    float*       __restrict__ final_out)
{
    extern __shared__ __align__(16) char sm[];
    ull   (*Wp)[WPAD]   = reinterpret_cast<ull(*)[WPAD]>(sm);             // 32*514*8 = 131584 B
    float (*hs)[64][68] = reinterpret_cast<float(*)[64][68]>(sm + 32 * WPAD * 8); // 2*64*68*4 = 34816 B

    const int tid  = threadIdx.x;
    const int j0   = blockIdx.x * 8;
    const int w    = tid >> 5;
    const int lane = tid & 31;
    const int gsel = lane >> 3;
    const int u    = lane & 7;

    // ---- load W_hh chunk into smem once (k-paired u64 layout) ----
    {
        const int wr = tid >> 3;             // 0..31 local row
        const int wk = (tid & 7) << 3;       // 0..56
        const int grow = (wr >> 3) * HID + j0 + (wr & 7);
        const float* wptr = Whh + (size_t)grow * HID + wk;
        for (int c = 0; c < 16; c++) {
            const int k0 = c * 64;
            float4 v0 = *(const float4*)(wptr + k0);
            float4 v1 = *(const float4*)(wptr + k0 + 4);
            *(float4*)&Wp[wr][(k0 + wk) >> 1]       = v0;
            *(float4*)&Wp[wr][((k0 + wk) >> 1) + 2] = v1;
        }
    }
    __syncthreads();

    const int   trn   = *training;
    const float scale = trn ? (1.0f / 0.9f) : 1.0f;

    const int hb = tid >> 2;            // 0..63 batch row (h loader)
    const int hk = (tid & 3) << 4;      // 0,16,32,48

    float creg[8];
    #pragma unroll
    for (int i = 0; i < 8; i++) creg[i] = 0.0f;

    #pragma unroll 1
    for (int t = 0; t < SEQLEN; t++) {
        // ---- grid barrier: wait for all CTAs to finish step t-1 ----
        if (t > 0) {
            if (tid == 0) {
                const unsigned int target = (unsigned int)NCTA * (unsigned int)t;
                unsigned int v;
                do {
                    asm volatile("ld.acquire.gpu.global.u32 %0, [%1];"
                                 : "=r"(v) : "l"(&g_bar) : "memory");
                } while (v < target);
            }
            __syncthreads();
        }

        const float* hin  = (t & 1) ? g_h1 : g_h0;
        float*       hout = (t == SEQLEN - 1) ? final_out : ((t & 1) ? g_h0 : g_h1);
        const float* Gt   = g_G + (size_t)t * BATCH * G4;

        // ---- prefetch G pre-activations and keep-mask (DRAM latency hidden) ----
        float garr[8];
        #pragma unroll
        for (int i = 0; i < 8; i++)
            garr[i] = __ldcg(&Gt[(size_t)(w * 8 + i) * G4 + gsel * HID + j0 + u]);
        float karr[8];
        if (trn && lane < 8) {
            #pragma unroll
            for (int i = 0; i < 8; i++)
                karr[i] = __ldcg(&keep[(size_t)t * BATCH * HID + (w * 8 + i) * HID + j0 + u]);
        }

        // ---- mainloop: h @ W^T over K=1024, double-buffered 64-k chunks ----
        ull acc[8];
        #pragma unroll
        for (int i = 0; i < 8; i++) acc[i] = 0ull;

        const float* hptr = hin + hb * HID + hk;
        float4 hreg[4];
        #pragma unroll
        for (int q = 0; q < 4; q++) hreg[q] = __ldcg((const float4*)(hptr + 4 * q));
        #pragma unroll
        for (int q = 0; q < 4; q++) *(float4*)&hs[0][hb][hk + 4 * q] = hreg[q];

        int buf = 0;
        #pragma unroll 1
        for (int c = 0; c < 16; c++) {
            __syncthreads();
            if (c < 15) {
                const int k1 = (c + 1) * 64;
                #pragma unroll
                for (int q = 0; q < 4; q++)
                    hreg[q] = __ldcg((const float4*)(hptr + k1 + 4 * q));
            }
            const int kbase = c << 5;   // (c*64)>>1
            #pragma unroll
            for (int kk = 0; kk < 64; kk += 4) {
                ulonglong2 wv = *(const ulonglong2*)&Wp[lane][kbase + (kk >> 1)];
                #pragma unroll
                for (int i = 0; i < 8; i++) {
                    ulonglong2 hv = *(const ulonglong2*)&hs[buf][w * 8 + i][kk];
                    ffma2(acc[i], wv.x, hv.x);
                    ffma2(acc[i], wv.y, hv.y);
                }
            }
            if (c < 15) {
                const int nb = buf ^ 1;
                #pragma unroll
                for (int q = 0; q < 4; q++) *(float4*)&hs[nb][hb][hk + 4 * q] = hreg[q];
            }
            buf ^= 1;
        }

        // ---- epilogue: gates, cell update (c in regs), dropout, h write ----
        #pragma unroll
        for (int i = 0; i < 8; i++) {
            const int b = w * 8 + i;
            float2 p = unpack2(acc[i]);
            float v = p.x + p.y + garr[i];
            float fv = __shfl_sync(0xffffffffu, v, lane + 8);
            float gv = __shfl_sync(0xffffffffu, v, lane + 16);
            float ov = __shfl_sync(0xffffffffu, v, lane + 24);
            if (lane < 8) {
                const int j = j0 + u;
                float ig = 1.0f / (1.0f + __expf(-v));
                float fg = 1.0f / (1.0f + __expf(-fv));
                float gg = tanhf(gv);
                float og = 1.0f / (1.0f + __expf(-ov));
                float cc = fg * creg[i] + ig * gg;
                creg[i] = cc;
                float h = og * tanhf(cc);
                if (trn) h *= karr[i] * scale;
                __stcg(&hout[b * HID + j], h);
            }
        }

        // ---- arrive: make h(t) visible, bump counter ----
        __threadfence();
        __syncthreads();
        if (tid == 0) atomicAdd(&g_bar, 1u);
    }
}

extern "C" void kernel_launch(void* const* d_in, const int* in_sizes, int n_in,
                              void* d_out, int out_size) {
    const float* x    = (const float*)d_in[0];
    const float* keep = (const float*)d_in[1];
    const float* Wih  = (const float*)d_in[2];
    const float* Whh  = (const float*)d_in[3];
    const float* bih  = (const float*)d_in[4];
    const float* bhh  = (const float*)d_in[5];
    const int*   trn  = (const int*)d_in[6];
    float* out = (float*)d_out;

    const int smem_bytes = 32 * WPAD * 8 + 2 * 64 * 68 * 4;   // 166400
    cudaFuncSetAttribute(lstm_persist, cudaFuncAttributeMaxDynamicSharedMemorySize, smem_bytes);

    zero_state_kernel<<<256, 256>>>();
    dim3 g1(32, 256);
    gemm_gates<<<g1, 256>>>(x, Wih, bih, bhh);
    lstm_persist<<<NCTA, 256, smem_bytes>>>(Whh, keep, trn, out);
}

// round 10
// speedup vs baseline: 2.2988x; 1.7565x over previous
#include <cuda_runtime.h>
#include <cuda_bf16.h>
#include <cstdint>

#define SEQLEN 512
#define BATCH  64
#define INP    1024
#define HID    1024
#define G4     4096
#define NCTA   128

typedef unsigned long long ull;

// ---- device scratch (static) ----
__device__ float g_G[(size_t)SEQLEN * BATCH * G4];
__device__ __nv_bfloat16 g_Whi[(size_t)G4 * HID];   // permuted: [cta][gate*8+u][k]
__device__ __nv_bfloat16 g_Wlo[(size_t)G4 * HID];
__device__ __nv_bfloat16 g_hhi[2][BATCH * HID];     // ping-pong (race fix)
__device__ __nv_bfloat16 g_hlo[2][BATCH * HID];
__device__ unsigned int g_bar;

// ---- f32x2 helpers (fp32 input GEMM) ----
static __device__ __forceinline__ void ffma2(ull& a, ull x, ull y) {
    asm("fma.rn.f32x2 %0, %1, %2, %0;" : "+l"(a) : "l"(x), "l"(y));
}
static __device__ __forceinline__ ull pack2(float x, float y) {
    ull r; asm("mov.b64 %0, {%1, %2};" : "=l"(r) : "f"(x), "f"(y)); return r;
}
static __device__ __forceinline__ float2 unpack2(ull v) {
    float lo, hi; asm("mov.b64 {%0, %1}, %2;" : "=f"(lo), "=f"(hi) : "l"(v));
    return make_float2(lo, hi);
}

// ---- warp MMA primitives (sm_80+ PTX; works on plain sm_103 target) ----
static __device__ __forceinline__ uint32_t smem_u32(const void* p) {
    uint32_t a;
    asm("{ .reg .u64 t; cvta.to.shared.u64 t, %1; cvt.u32.u64 %0, t; }" : "=r"(a) : "l"(p));
    return a;
}
static __device__ __forceinline__ void ldsm4(uint32_t& r0, uint32_t& r1,
                                             uint32_t& r2, uint32_t& r3, uint32_t a) {
    asm volatile("ldmatrix.sync.aligned.m8n8.x4.shared.b16 {%0,%1,%2,%3}, [%4];"
                 : "=r"(r0), "=r"(r1), "=r"(r2), "=r"(r3) : "r"(a));
}
static __device__ __forceinline__ void mma16816(float* d, const uint32_t* a,
                                                uint32_t b0, uint32_t b1) {
    asm volatile("mma.sync.aligned.m16n8k16.row.col.f32.bf16.bf16.f32 "
                 "{%0,%1,%2,%3}, {%4,%5,%6,%7}, {%8,%9}, {%0,%1,%2,%3};"
                 : "+f"(d[0]), "+f"(d[1]), "+f"(d[2]), "+f"(d[3])
                 : "r"(a[0]), "r"(a[1]), "r"(a[2]), "r"(a[3]), "r"(b0), "r"(b1));
}
static __device__ __forceinline__ void cpa16(uint32_t dst, const void* src) {
    asm volatile("cp.async.cg.shared.global [%0], [%1], 16;" :: "r"(dst), "l"(src));
}
#define CP_COMMIT() asm volatile("cp.async.commit_group;" ::: "memory")
#define CP_WAIT1()  asm volatile("cp.async.wait_group 1;" ::: "memory")
#define CP_WAIT0()  asm volatile("cp.async.wait_group 0;" ::: "memory")

// ---- init ----
__global__ void zero_state_kernel() {
    int i = blockIdx.x * blockDim.x + threadIdx.x;
    if (i < BATCH * HID) {
        g_hhi[0][i] = __float2bfloat16(0.0f);
        g_hlo[0][i] = __float2bfloat16(0.0f);
        g_hhi[1][i] = __float2bfloat16(0.0f);
        g_hlo[1][i] = __float2bfloat16(0.0f);
    }
    if (i == 0) g_bar = 0u;
}

// ---- split + permute W_hh: cta = j>>3 (128 ctas), local row = gate*8 + (j&7) ----
__global__ void wsplit_kernel(const float* __restrict__ Whh) {
    int idx = blockIdx.x * blockDim.x + threadIdx.x;
    if (idx >= G4 * HID) return;
    int gr = idx >> 10;
    int k  = idx & 1023;
    int gate = gr >> 10;
    int j    = gr & 1023;
    int cta  = j >> 3;
    int u    = j & 7;
    size_t dst = ((size_t)cta * 32 + gate * 8 + u) * 1024 + k;
    float w = Whh[(size_t)gr * 1024 + k];
    __nv_bfloat16 hi = __float2bfloat16(w);
    float res = w - __bfloat162float(hi);
    g_Whi[dst] = hi;
    g_Wlo[dst] = __float2bfloat16(res);
}

// ---- big input GEMM (proven): G = X @ W_ih^T + (b_ih + b_hh) ----
__global__ __launch_bounds__(256) void gemm_gates(
    const float* __restrict__ X, const float* __restrict__ Wih,
    const float* __restrict__ bih, const float* __restrict__ bhh)
{
    __shared__ __align__(16) float As[8][132];
    __shared__ __align__(16) float Bs[8][132];
    const int tid = threadIdx.x;
    const int bn = blockIdx.x, bm = blockIdx.y;
    const int lr = tid >> 1, lk = (tid & 1) << 2;
    const float* Ag = X   + (size_t)(bm * 128 + lr) * INP + lk;
    const float* Bg = Wih + (size_t)(bn * 128 + lr) * INP + lk;
    const int tx = tid & 15, ty = tid >> 4;

    ull acc[8][4];
    #pragma unroll
    for (int i = 0; i < 8; i++)
        #pragma unroll
        for (int j = 0; j < 4; j++) acc[i][j] = 0ull;

    for (int k0 = 0; k0 < INP; k0 += 8) {
        float4 av = *(const float4*)(Ag + k0);
        float4 bv = *(const float4*)(Bg + k0);
        __syncthreads();
        As[lk+0][lr] = av.x; As[lk+1][lr] = av.y; As[lk+2][lr] = av.z; As[lk+3][lr] = av.w;
        Bs[lk+0][lr] = bv.x; Bs[lk+1][lr] = bv.y; Bs[lk+2][lr] = bv.z; Bs[lk+3][lr] = bv.w;
        __syncthreads();
        #pragma unroll
        for (int kk = 0; kk < 8; kk++) {
            float4 a0 = *(const float4*)&As[kk][ty * 8];
            float4 a1 = *(const float4*)&As[kk][ty * 8 + 4];
            ulonglong2 b0 = *(const ulonglong2*)&Bs[kk][tx * 8];
            ulonglong2 b1 = *(const ulonglong2*)&Bs[kk][tx * 8 + 4];
            float a[8] = {a0.x,a0.y,a0.z,a0.w,a1.x,a1.y,a1.z,a1.w};
            #pragma unroll
            for (int i = 0; i < 8; i++) {
                ull aa = pack2(a[i], a[i]);
                ffma2(acc[i][0], aa, b0.x); ffma2(acc[i][1], aa, b0.y);
                ffma2(acc[i][2], aa, b1.x); ffma2(acc[i][3], aa, b1.y);
            }
        }
    }
    const int col0 = bn * 128 + tx * 8;
    float bias[8];
    #pragma unroll
    for (int j = 0; j < 8; j++) bias[j] = bih[col0 + j] + bhh[col0 + j];
    #pragma unroll
    for (int i = 0; i < 8; i++) {
        int row = bm * 128 + ty * 8 + i;
        float2 p0 = unpack2(acc[i][0]), p1 = unpack2(acc[i][1]);
        float2 p2 = unpack2(acc[i][2]), p3 = unpack2(acc[i][3]);
        float4 o0 = make_float4(p0.x+bias[0], p0.y+bias[1], p1.x+bias[2], p1.y+bias[3]);
        float4 o1 = make_float4(p2.x+bias[4], p2.y+bias[5], p3.x+bias[6], p3.y+bias[7]);
        *(float4*)&g_G[(size_t)row * G4 + col0    ] = o0;
        *(float4*)&g_G[(size_t)row * G4 + col0 + 4] = o1;
    }
}

// ---- smem layout (bytes) ----
#define WSTRIDE   1032                      // halves per W row (pad 8 -> conflict-free)
#define SM_W      0                         // Whi [32][1032], then Wlo
#define WHALF_SZ  (32 * WSTRIDE * 2)        // 66048
#define SM_H      (2 * WHALF_SZ)            // 132096
#define HSTRIDE   72                        // halves per h row (pad 8)
#define HB_SZ     (64 * HSTRIDE * 2)        // 9216 per (hi/lo)
#define HBUF_SZ   (2 * HB_SZ)               // hi+lo per buffer
#define SM_GATES  (SM_H + 2 * HBUF_SZ)      // float[32][68]
#define SM_TOTAL  (SM_GATES + 32 * 68 * 4)  // 177664

static __device__ __forceinline__ void issue_chunk(
    int c, uint32_t hbuf, const char* hhi, const char* hlo, int tid)
{
    #pragma unroll
    for (int r = 0; r < 2; r++) {
        int i = tid + r * 256;              // 0..511
        int row = i >> 3, seg = i & 7;
        uint32_t d = hbuf + row * (HSTRIDE * 2) + seg * 16;
        cpa16(d,         hhi + (size_t)row * 2048 + c * 128 + seg * 16);
        cpa16(d + HB_SZ, hlo + (size_t)row * 2048 + c * 128 + seg * 16);
    }
}

// ---- persistent recurrence on HMMA tensor cores ----
// 128 CTAs x 256 thr (8 warps = 2M x 4N). CTA: 32 D-rows (4 gates x 8 units), N=64, K=1024.
__global__ __launch_bounds__(256) void lstm_persist(
    const float* __restrict__ keep,
    const int*   __restrict__ training,
    float*       __restrict__ final_out)
{
    extern __shared__ __align__(16) char sm[];
    const uint32_t smb = smem_u32(sm);
    const int tid  = threadIdx.x;
    const int wid  = tid >> 5;
    const int lane = tid & 31;
    const int cta  = blockIdx.x;

    // load W slice into smem once
    {
        const char* whi = (const char*)(g_Whi + (size_t)cta * 32 * 1024);
        const char* wlo = (const char*)(g_Wlo + (size_t)cta * 32 * 1024);
        for (int i = tid; i < 4096; i += 256) {     // 32 rows x 128 16B-segs
            int row = i >> 7, seg = i & 127;
            uint32_t off = row * (WSTRIDE * 2) + seg * 16;
            *(uint4*)(sm + SM_W + off)            = *(const uint4*)(whi + row * 2048 + seg * 16);
            *(uint4*)(sm + SM_W + WHALF_SZ + off) = *(const uint4*)(wlo + row * 2048 + seg * 16);
        }
    }
    __syncthreads();

    const int   trn   = *training;
    const float scale = trn ? (1.0f / 0.9f) : 1.0f;

    // MMA tiling
    const int wm = wid >> 2;            // 0..1 (16 rows each)
    const int wn = wid & 3;             // 0..3 (16 cols each)
    const int lr = lane & 7;
    const int g  = lane >> 3;
    const uint32_t aoff = smb + SM_W +
        (uint32_t)((wm * 16 + lr + ((g & 1) << 3)) * WSTRIDE + ((g >> 1) << 3)) * 2;
    const uint32_t boff =
        (uint32_t)((wn * 16 + lr + ((g >> 1) << 3)) * HSTRIDE + ((g & 1) << 3)) * 2;

    float* gates = (float*)(sm + SM_GATES);

    // cell mapping: unit u = tid>>5, batches 2*(tid&31)+{0,1}
    const int u  = tid >> 5;
    const int b2 = tid & 31;
    const int j  = cta * 8 + u;

    float creg[2] = {0.0f, 0.0f};

    #pragma unroll 1
    for (int t = 0; t < SEQLEN; t++) {
        const int rb = t & 1;                       // read h(t-1) from buffer rb
        const char* hhi = (const char*)g_hhi[rb];
        const char* hlo = (const char*)g_hlo[rb];

        // prefetch G + keep (independent of h; overlaps barrier wait)
        float garr[8], karr[2];
        #pragma unroll
        for (int gg = 0; gg < 4; gg++)
            #pragma unroll
            for (int i = 0; i < 2; i++)
                garr[gg * 2 + i] =
                    __ldcg(&g_G[((size_t)t * BATCH + 2 * b2 + i) * G4 + gg * 1024 + j]);
        if (trn) {
            #pragma unroll
            for (int i = 0; i < 2; i++)
                karr[i] = __ldcg(&keep[((size_t)t * BATCH + 2 * b2 + i) * HID + j]);
        }

        // grid barrier: h(t-1) visible everywhere
        if (t > 0) {
            if (tid == 0) {
                const unsigned int target = (unsigned int)NCTA * (unsigned int)t;
                unsigned int v;
                do {
                    asm volatile("ld.acquire.gpu.global.u32 %0, [%1];"
                                 : "=r"(v) : "l"(&g_bar) : "memory");
                } while (v < target);
            }
            __syncthreads();
        }

        issue_chunk(0, smb + SM_H, hhi, hlo, tid); CP_COMMIT();
        issue_chunk(1, smb + SM_H + HBUF_SZ, hhi, hlo, tid); CP_COMMIT();

        float acc0[4] = {0, 0, 0, 0}, acc1[4] = {0, 0, 0, 0};

        #pragma unroll 1
        for (int c = 0; c < 16; c++) {
            if (c < 15) { CP_WAIT1(); } else { CP_WAIT0(); }
            __syncthreads();

            const uint32_t hb = smb + SM_H + (c & 1) * HBUF_SZ;
            const uint32_t ac = aoff + c * 128;     // FIX: W k-offset per chunk
            #pragma unroll
            for (int ks = 0; ks < 4; ks++) {
                const uint32_t kb = ks * 32;
                uint32_t ah[4], al[4], bh[4], bl[4];
                ldsm4(ah[0], ah[1], ah[2], ah[3], ac + kb);
                ldsm4(al[0], al[1], al[2], al[3], ac + WHALF_SZ + kb);
                ldsm4(bh[0], bh[1], bh[2], bh[3], hb + boff + kb);
                ldsm4(bl[0], bl[1], bl[2], bl[3], hb + boff + HB_SZ + kb);
                mma16816(acc0, ah, bh[0], bh[1]);
                mma16816(acc0, ah, bl[0], bl[1]);
                mma16816(acc0, al, bh[0], bh[1]);
                mma16816(acc1, ah, bh[2], bh[3]);
                mma16816(acc1, ah, bl[2], bl[3]);
                mma16816(acc1, al, bh[2], bh[3]);
            }
            __syncthreads();
            if (c + 2 < 16) { issue_chunk(c + 2, hb, hhi, hlo, tid); CP_COMMIT(); }
        }

        // D -> gates smem
        {
            const int r = lane >> 2, cb = (lane & 3) * 2;
            float* g0 = &gates[(wm * 16 + r) * 68 + wn * 16 + cb];
            float* g1 = &gates[(wm * 16 + r + 8) * 68 + wn * 16 + cb];
            g0[0] = acc0[0]; g0[1] = acc0[1];
            g1[0] = acc0[2]; g1[1] = acc0[3];
            g0[8] = acc1[0]; g0[9] = acc1[1];
            g1[8] = acc1[2]; g1[9] = acc1[3];
        }
        __syncthreads();

        // cell update; write h(t) into buffer rb^1
        __nv_bfloat16* whhi = g_hhi[rb ^ 1];
        __nv_bfloat16* whlo = g_hlo[rb ^ 1];
        #pragma unroll
        for (int i = 0; i < 2; i++) {
            const int b = 2 * b2 + i;
            float iv = gates[(0 * 8 + u) * 68 + b] + garr[0 * 2 + i];
            float fv = gates[(1 * 8 + u) * 68 + b] + garr[1 * 2 + i];
            float gv = gates[(2 * 8 + u) * 68 + b] + garr[2 * 2 + i];
            float ov = gates[(3 * 8 + u) * 68 + b] + garr[3 * 2 + i];
            float ig = 1.0f / (1.0f + __expf(-iv));
            float fg = 1.0f / (1.0f + __expf(-fv));
            float gg = tanhf(gv);
            float og = 1.0f / (1.0f + __expf(-ov));
            float cc = fg * creg[i] + ig * gg;
            creg[i] = cc;
            float h = og * tanhf(cc);
            if (trn) h *= karr[i] * scale;
            __nv_bfloat16 hh = __float2bfloat16(h);
            float res = h - __bfloat162float(hh);
            __stcg(&whhi[b * HID + j], hh);
            __stcg(&whlo[b * HID + j], __float2bfloat16(res));
            if (t == SEQLEN - 1) final_out[b * HID + j] = h;
        }

        __threadfence();
        __syncthreads();
        if (tid == 0) atomicAdd(&g_bar, 1u);
    }
}

extern "C" void kernel_launch(void* const* d_in, const int* in_sizes, int n_in,
                              void* d_out, int out_size) {
    const float* x    = (const float*)d_in[0];
    const float* keep = (const float*)d_in[1];
    const float* Wih  = (const float*)d_in[2];
    const float* Whh  = (const float*)d_in[3];
    const float* bih  = (const float*)d_in[4];
    const float* bhh  = (const float*)d_in[5];
    const int*   trn  = (const int*)d_in[6];
    float* out = (float*)d_out;

    cudaFuncSetAttribute(lstm_persist, cudaFuncAttributeMaxDynamicSharedMemorySize, SM_TOTAL);

    zero_state_kernel<<<256, 256>>>();
    wsplit_kernel<<<(G4 * HID + 255) / 256, 256>>>(Whh);
    dim3 g1(32, 256);
    gemm_gates<<<g1, 256>>>(x, Wih, bih, bhh);
    lstm_persist<<<NCTA, 256, SM_TOTAL>>>(keep, trn, out);
}